// round 7
// baseline (speedup 1.0000x reference)
#include <cuda_runtime.h>
#include <math.h>

#define N_NODES 50000
#define N_EDGES 800000
#define F_IN    32
#define H_DIM   64
#define C_OUT   7
#define C_PAD   8
#define BN_EPS  1e-5f

// ---------------- scratch (device globals; no allocation) ----------------
__device__ __align__(128) float g_Y0[N_NODES * H_DIM];   // x @ W[0]            (padded rows)
__device__ __align__(128) float g_Y1[N_NODES * H_DIM];   // x @ (W[1]-W[0])
__device__ __align__(128) float g_Z [N_NODES * H_DIM];   // x @ R + B
__device__ __align__(128) float g_A [N_NODES * H_DIM];   // edge aggregation accumulator
__device__ __align__(128) float g_H [N_NODES * H_DIM];   // hidden activations between layers
__device__ __align__(128) int   g_cnt[N_NODES];          // in-degree

// ---------------- small utility kernels ----------------
__global__ void zero_cnt_kernel() {
    int i = blockIdx.x * blockDim.x + threadIdx.x;
    if (i < N_NODES) g_cnt[i] = 0;
}

__global__ void deg_kernel(const int* __restrict__ ei) {
    int e = blockIdx.x * blockDim.x + threadIdx.x;
    if (e < N_EDGES) atomicAdd(&g_cnt[ei[N_EDGES + e]], 1);
}

__global__ void zeroA_kernel(int n4) {
    int i = blockIdx.x * blockDim.x + threadIdx.x;
    if (i < n4) reinterpret_cast<float4*>(g_A)[i] = make_float4(0.f, 0.f, 0.f, 0.f);
}

// ---------------- fused node-side GEMM: Y0 = X@W0, Y1 = X@(W1-W0), Z = X@R + B ----------------
// blockDim = (COUTP, 256/COUTP). Each thread owns output column o for NT nodes.
template<int CIN, int COUT, int COUTP, int NT>
__global__ void __launch_bounds__(256)
gemm3_kernel(const float* __restrict__ Xext,
             const float* __restrict__ W,     // [2][CIN][COUT]
             const float* __restrict__ R,     // [CIN][COUT]
             const float* __restrict__ B,     // [COUT]
             int use_h)
{
    constexpr int TY    = 256 / COUTP;
    constexpr int NODES = TY * NT;
    __shared__ float sx[NODES][CIN];

    const float* X = use_h ? (const float*)g_H : Xext;

    int nbase_blk = blockIdx.x * NODES;
    int tid = threadIdx.y * COUTP + threadIdx.x;

    // cooperative, vectorized staging of NODES feature rows
    constexpr int NV = NODES * CIN / 4;
    const float4* X4 = reinterpret_cast<const float4*>(X);
    float4* sx4 = reinterpret_cast<float4*>(&sx[0][0]);
    #pragma unroll
    for (int i = tid; i < NV; i += 256) {
        int nn = nbase_blk + i / (CIN / 4);
        float4 v = make_float4(0.f, 0.f, 0.f, 0.f);
        if (nn < N_NODES) v = X4[nn * (CIN / 4) + (i % (CIN / 4))];
        sx4[i] = v;
    }
    __syncthreads();

    int o  = threadIdx.x;
    int nb = threadIdx.y * NT;

    float a0[NT], a1[NT], az[NT];
    #pragma unroll
    for (int j = 0; j < NT; j++) { a0[j] = 0.f; a1[j] = 0.f; az[j] = 0.f; }

    float b = 0.f;
    if (o < COUT) {
        b = B[o];
        #pragma unroll 4
        for (int c = 0; c < CIN; c++) {
            float w0 = W[c * COUT + o];
            float w1 = W[CIN * COUT + c * COUT + o];
            float r  = R[c * COUT + o];
            float dw = w1 - w0;
            #pragma unroll
            for (int j = 0; j < NT; j++) {
                float xv = sx[nb + j][c];
                a0[j] = fmaf(xv, w0, a0[j]);
                a1[j] = fmaf(xv, dw, a1[j]);
                az[j] = fmaf(xv, r,  az[j]);
            }
        }
    }

    #pragma unroll
    for (int j = 0; j < NT; j++) {
        int n = nbase_blk + nb + j;
        if (n < N_NODES) {
            g_Y0[n * COUTP + o] = a0[j];
            g_Y1[n * COUTP + o] = a1[j];
            g_Z [n * COUTP + o] = az[j] + b;   // pad columns get exact 0
        }
    }
}

// ---------------- edge scatter: A[dst] += Y0[src] + u * Y1[src]  (vectorized red.v4) ----------------
template<int COUTP>
__global__ void scatter_kernel(const int* __restrict__ ei, const float* __restrict__ ea)
{
    constexpr int Q = COUTP / 4;
    int idx = blockIdx.x * blockDim.x + threadIdx.x;
    if (idx >= N_EDGES * Q) return;
    int e = idx / Q;           // power-of-2 -> shift
    int q = idx - e * Q;

    int   s = ei[e];
    int   d = ei[N_EDGES + e];
    float u = ea[e];

    const float4* Y04 = reinterpret_cast<const float4*>(g_Y0);
    const float4* Y14 = reinterpret_cast<const float4*>(g_Y1);
    float4 v0 = Y04[s * Q + q];
    float4 v1 = Y14[s * Q + q];
    float4 m;
    m.x = fmaf(u, v1.x, v0.x);
    m.y = fmaf(u, v1.y, v0.y);
    m.z = fmaf(u, v1.z, v0.z);
    m.w = fmaf(u, v1.w, v0.w);

    float* dst = &g_A[d * COUTP + q * 4];
    asm volatile("red.global.add.v4.f32 [%0], {%1,%2,%3,%4};"
                 :: "l"(dst), "f"(m.x), "f"(m.y), "f"(m.z), "f"(m.w) : "memory");
}

// ---------------- epilogue for hidden layers: mean + residual + BN + ELU -> g_H ----------------
__global__ void epi_bn_kernel(const float* __restrict__ G,  const float* __restrict__ BE,
                              const float* __restrict__ RM, const float* __restrict__ RV)
{
    int idx = blockIdx.x * blockDim.x + threadIdx.x;
    if (idx >= N_NODES * H_DIM) return;
    int n = idx >> 6;
    int o = idx & 63;
    int cnt = g_cnt[n];
    float inv = 1.f / (float)(cnt < 1 ? 1 : cnt);
    float v = g_A[idx] * inv + g_Z[idx];
    v = (v - RM[o]) * rsqrtf(RV[o] + BN_EPS) * G[o] + BE[o];
    v = (v > 0.f) ? v : expm1f(v);
    g_H[idx] = v;
}

// ---------------- final epilogue: mean + residual + log_softmax over 7 classes ----------------
__global__ void final_kernel(float* __restrict__ out)
{
    int n = blockIdx.x * blockDim.x + threadIdx.x;
    if (n >= N_NODES) return;
    int cnt = g_cnt[n];
    float inv = 1.f / (float)(cnt < 1 ? 1 : cnt);

    float v[C_OUT];
    float mx = -INFINITY;
    #pragma unroll
    for (int o = 0; o < C_OUT; o++) {
        float t = g_A[n * C_PAD + o] * inv + g_Z[n * C_PAD + o];
        v[o] = t;
        mx = fmaxf(mx, t);
    }
    float s = 0.f;
    #pragma unroll
    for (int o = 0; o < C_OUT; o++) s += __expf(v[o] - mx);
    float lse = mx + logf(s);
    #pragma unroll
    for (int o = 0; o < C_OUT; o++) out[n * C_OUT + o] = v[o] - lse;
}

// ---------------- launch ----------------
extern "C" void kernel_launch(void* const* d_in, const int* in_sizes, int n_in,
                              void* d_out, int out_size)
{
    const float* x   = (const float*)d_in[0];
    const int*   ei  = (const int*)  d_in[1];
    const float* ea  = (const float*)d_in[2];
    const float* W0  = (const float*)d_in[3];
    const float* R0  = (const float*)d_in[4];
    const float* B0  = (const float*)d_in[5];
    const float* W1  = (const float*)d_in[6];
    const float* R1  = (const float*)d_in[7];
    const float* B1  = (const float*)d_in[8];
    const float* W2  = (const float*)d_in[9];
    const float* R2  = (const float*)d_in[10];
    const float* B2  = (const float*)d_in[11];
    const float* G0  = (const float*)d_in[12];
    const float* BE0 = (const float*)d_in[13];
    const float* RM0 = (const float*)d_in[14];
    const float* RV0 = (const float*)d_in[15];
    const float* G1  = (const float*)d_in[16];
    const float* BE1 = (const float*)d_in[17];
    const float* RM1 = (const float*)d_in[18];
    const float* RV1 = (const float*)d_in[19];
    float* out = (float*)d_out;

    // degrees (constant across layers)
    zero_cnt_kernel<<<(N_NODES + 255) / 256, 256>>>();
    deg_kernel<<<(N_EDGES + 255) / 256, 256>>>(ei);

    // ---- Layer 0: F_IN=32 -> H=64 ----
    gemm3_kernel<32, 64, 64, 8><<<(N_NODES + 31) / 32, dim3(64, 4)>>>(x, W0, R0, B0, 0);
    zeroA_kernel<<<(N_NODES * 64 / 4 + 255) / 256, 256>>>(N_NODES * 64 / 4);
    scatter_kernel<64><<<(N_EDGES * 16 + 255) / 256, 256>>>(ei, ea);
    epi_bn_kernel<<<(N_NODES * 64 + 255) / 256, 256>>>(G0, BE0, RM0, RV0);

    // ---- Layer 1: H=64 -> H=64 ----
    gemm3_kernel<64, 64, 64, 8><<<(N_NODES + 31) / 32, dim3(64, 4)>>>(nullptr, W1, R1, B1, 1);
    zeroA_kernel<<<(N_NODES * 64 / 4 + 255) / 256, 256>>>(N_NODES * 64 / 4);
    scatter_kernel<64><<<(N_EDGES * 16 + 255) / 256, 256>>>(ei, ea);
    epi_bn_kernel<<<(N_NODES * 64 + 255) / 256, 256>>>(G1, BE1, RM1, RV1);

    // ---- Layer 2: H=64 -> C=7 (padded to 8) ----
    gemm3_kernel<64, 7, 8, 2><<<(N_NODES + 63) / 64, dim3(8, 32)>>>(nullptr, W2, R2, B2, 1);
    zeroA_kernel<<<(N_NODES * 8 / 4 + 255) / 256, 256>>>(N_NODES * 8 / 4);
    scatter_kernel<8><<<(N_EDGES * 2 + 255) / 256, 256>>>(ei, ea);
    final_kernel<<<(N_NODES + 255) / 256, 256>>>(out);
}

// round 8
// speedup vs baseline: 1.0069x; 1.0069x over previous
#include <cuda_runtime.h>
#include <math.h>

#define N_NODES 50000
#define N_EDGES 800000
#define F_IN    32
#define H_DIM   64
#define C_OUT   7
#define C_PAD   8
#define BN_EPS  1e-5f

// ---------------- scratch (device globals; no allocation) ----------------
__device__ __align__(128) float g_Y0[N_NODES * H_DIM];   // x @ W[0]            (padded rows)
__device__ __align__(128) float g_Y1[N_NODES * H_DIM];   // x @ (W[1]-W[0])
__device__ __align__(128) float g_Z [N_NODES * H_DIM];   // x @ R + B
__device__ __align__(128) float g_A [N_NODES * H_DIM];   // edge aggregation accumulator
__device__ __align__(128) float g_H [N_NODES * H_DIM];   // hidden activations between layers
__device__ __align__(128) int   g_cnt[N_NODES];          // in-degree

// ---------------- small utility kernels ----------------
__global__ void zero_cnt_kernel() {
    int i = blockIdx.x * blockDim.x + threadIdx.x;
    if (i < N_NODES) g_cnt[i] = 0;
}

__global__ void deg_kernel(const int* __restrict__ ei) {
    int e = blockIdx.x * blockDim.x + threadIdx.x;
    if (e < N_EDGES) atomicAdd(&g_cnt[ei[N_EDGES + e]], 1);
}

__global__ void zeroA_kernel(int n4) {
    int i = blockIdx.x * blockDim.x + threadIdx.x;
    if (i < n4) reinterpret_cast<float4*>(g_A)[i] = make_float4(0.f, 0.f, 0.f, 0.f);
}

// ---------------- fused node-side GEMM: Y0 = X@W0, Y1 = X@(W1-W0), Z = X@R + B ----------------
// blockDim = (COUTP, 256/COUTP). Each thread owns output column o for NT nodes.
template<int CIN, int COUT, int COUTP, int NT>
__global__ void __launch_bounds__(256)
gemm3_kernel(const float* __restrict__ Xext,
             const float* __restrict__ W,     // [2][CIN][COUT]
             const float* __restrict__ R,     // [CIN][COUT]
             const float* __restrict__ B,     // [COUT]
             int use_h)
{
    constexpr int TY    = 256 / COUTP;
    constexpr int NODES = TY * NT;
    __shared__ float sx[NODES][CIN];

    const float* X = use_h ? (const float*)g_H : Xext;

    int nbase_blk = blockIdx.x * NODES;
    int tid = threadIdx.y * COUTP + threadIdx.x;

    // cooperative, vectorized staging of NODES feature rows
    constexpr int NV = NODES * CIN / 4;
    const float4* X4 = reinterpret_cast<const float4*>(X);
    float4* sx4 = reinterpret_cast<float4*>(&sx[0][0]);
    #pragma unroll
    for (int i = tid; i < NV; i += 256) {
        int nn = nbase_blk + i / (CIN / 4);
        float4 v = make_float4(0.f, 0.f, 0.f, 0.f);
        if (nn < N_NODES) v = X4[nn * (CIN / 4) + (i % (CIN / 4))];
        sx4[i] = v;
    }
    __syncthreads();

    int o  = threadIdx.x;
    int nb = threadIdx.y * NT;

    float a0[NT], a1[NT], az[NT];
    #pragma unroll
    for (int j = 0; j < NT; j++) { a0[j] = 0.f; a1[j] = 0.f; az[j] = 0.f; }

    float b = 0.f;
    if (o < COUT) {
        b = B[o];
        #pragma unroll 4
        for (int c = 0; c < CIN; c++) {
            float w0 = W[c * COUT + o];
            float w1 = W[CIN * COUT + c * COUT + o];
            float r  = R[c * COUT + o];
            float dw = w1 - w0;
            #pragma unroll
            for (int j = 0; j < NT; j++) {
                float xv = sx[nb + j][c];
                a0[j] = fmaf(xv, w0, a0[j]);
                a1[j] = fmaf(xv, dw, a1[j]);
                az[j] = fmaf(xv, r,  az[j]);
            }
        }
    }

    #pragma unroll
    for (int j = 0; j < NT; j++) {
        int n = nbase_blk + nb + j;
        if (n < N_NODES) {
            g_Y0[n * COUTP + o] = a0[j];
            g_Y1[n * COUTP + o] = a1[j];
            g_Z [n * COUTP + o] = az[j] + b;   // pad columns get exact 0
        }
    }
}

// ---------------- edge scatter: A[dst] += Y0[src] + u * Y1[src]  (vectorized red.v4) ----------------
template<int COUTP>
__global__ void scatter_kernel(const int* __restrict__ ei, const float* __restrict__ ea)
{
    constexpr int Q = COUTP / 4;
    int idx = blockIdx.x * blockDim.x + threadIdx.x;
    if (idx >= N_EDGES * Q) return;
    int e = idx / Q;           // power-of-2 -> shift
    int q = idx - e * Q;

    int   s = ei[e];
    int   d = ei[N_EDGES + e];
    float u = ea[e];

    const float4* Y04 = reinterpret_cast<const float4*>(g_Y0);
    const float4* Y14 = reinterpret_cast<const float4*>(g_Y1);
    float4 v0 = Y04[s * Q + q];
    float4 v1 = Y14[s * Q + q];
    float4 m;
    m.x = fmaf(u, v1.x, v0.x);
    m.y = fmaf(u, v1.y, v0.y);
    m.z = fmaf(u, v1.z, v0.z);
    m.w = fmaf(u, v1.w, v0.w);

    float* dst = &g_A[d * COUTP + q * 4];
    asm volatile("red.global.add.v4.f32 [%0], {%1,%2,%3,%4};"
                 :: "l"(dst), "f"(m.x), "f"(m.y), "f"(m.z), "f"(m.w) : "memory");
}

// ---------------- epilogue for hidden layers: mean + residual + BN + ELU -> g_H ----------------
__global__ void epi_bn_kernel(const float* __restrict__ G,  const float* __restrict__ BE,
                              const float* __restrict__ RM, const float* __restrict__ RV)
{
    int idx = blockIdx.x * blockDim.x + threadIdx.x;
    if (idx >= N_NODES * H_DIM) return;
    int n = idx >> 6;
    int o = idx & 63;
    int cnt = g_cnt[n];
    float inv = 1.f / (float)(cnt < 1 ? 1 : cnt);
    float v = g_A[idx] * inv + g_Z[idx];
    v = (v - RM[o]) * rsqrtf(RV[o] + BN_EPS) * G[o] + BE[o];
    v = (v > 0.f) ? v : expm1f(v);
    g_H[idx] = v;
}

// ---------------- final epilogue: mean + residual + log_softmax over 7 classes ----------------
__global__ void final_kernel(float* __restrict__ out)
{
    int n = blockIdx.x * blockDim.x + threadIdx.x;
    if (n >= N_NODES) return;
    int cnt = g_cnt[n];
    float inv = 1.f / (float)(cnt < 1 ? 1 : cnt);

    float v[C_OUT];
    float mx = -INFINITY;
    #pragma unroll
    for (int o = 0; o < C_OUT; o++) {
        float t = g_A[n * C_PAD + o] * inv + g_Z[n * C_PAD + o];
        v[o] = t;
        mx = fmaxf(mx, t);
    }
    float s = 0.f;
    #pragma unroll
    for (int o = 0; o < C_OUT; o++) s += __expf(v[o] - mx);
    float lse = mx + logf(s);
    #pragma unroll
    for (int o = 0; o < C_OUT; o++) out[n * C_OUT + o] = v[o] - lse;
}

// ---------------- launch ----------------
extern "C" void kernel_launch(void* const* d_in, const int* in_sizes, int n_in,
                              void* d_out, int out_size)
{
    const float* x   = (const float*)d_in[0];
    const int*   ei  = (const int*)  d_in[1];
    const float* ea  = (const float*)d_in[2];
    const float* W0  = (const float*)d_in[3];
    const float* R0  = (const float*)d_in[4];
    const float* B0  = (const float*)d_in[5];
    const float* W1  = (const float*)d_in[6];
    const float* R1  = (const float*)d_in[7];
    const float* B1  = (const float*)d_in[8];
    const float* W2  = (const float*)d_in[9];
    const float* R2  = (const float*)d_in[10];
    const float* B2  = (const float*)d_in[11];
    const float* G0  = (const float*)d_in[12];
    const float* BE0 = (const float*)d_in[13];
    const float* RM0 = (const float*)d_in[14];
    const float* RV0 = (const float*)d_in[15];
    const float* G1  = (const float*)d_in[16];
    const float* BE1 = (const float*)d_in[17];
    const float* RM1 = (const float*)d_in[18];
    const float* RV1 = (const float*)d_in[19];
    float* out = (float*)d_out;

    // degrees (constant across layers)
    zero_cnt_kernel<<<(N_NODES + 255) / 256, 256>>>();
    deg_kernel<<<(N_EDGES + 255) / 256, 256>>>(ei);

    // ---- Layer 0: F_IN=32 -> H=64 ----
    gemm3_kernel<32, 64, 64, 8><<<(N_NODES + 31) / 32, dim3(64, 4)>>>(x, W0, R0, B0, 0);
    zeroA_kernel<<<(N_NODES * 64 / 4 + 255) / 256, 256>>>(N_NODES * 64 / 4);
    scatter_kernel<64><<<(N_EDGES * 16 + 255) / 256, 256>>>(ei, ea);
    epi_bn_kernel<<<(N_NODES * 64 + 255) / 256, 256>>>(G0, BE0, RM0, RV0);

    // ---- Layer 1: H=64 -> H=64 ----
    gemm3_kernel<64, 64, 64, 8><<<(N_NODES + 31) / 32, dim3(64, 4)>>>(nullptr, W1, R1, B1, 1);
    zeroA_kernel<<<(N_NODES * 64 / 4 + 255) / 256, 256>>>(N_NODES * 64 / 4);
    scatter_kernel<64><<<(N_EDGES * 16 + 255) / 256, 256>>>(ei, ea);
    epi_bn_kernel<<<(N_NODES * 64 + 255) / 256, 256>>>(G1, BE1, RM1, RV1);

    // ---- Layer 2: H=64 -> C=7 (padded to 8) ----
    gemm3_kernel<64, 7, 8, 2><<<(N_NODES + 63) / 64, dim3(8, 32)>>>(nullptr, W2, R2, B2, 1);
    zeroA_kernel<<<(N_NODES * 8 / 4 + 255) / 256, 256>>>(N_NODES * 8 / 4);
    scatter_kernel<8><<<(N_EDGES * 2 + 255) / 256, 256>>>(ei, ea);
    final_kernel<<<(N_NODES + 255) / 256, 256>>>(out);
}